// round 1
// baseline (speedup 1.0000x reference)
#include <cuda_runtime.h>

#define CB 16
#define CN 1024
#define CD 512
#define CH 8
#define CKD 64
#define CM (CB * CN)  // 16384

// Scratch (alloc-free rule: __device__ globals)
__device__ float g_Q[(size_t)CB * CH * CN * CKD];   // 32 MB, [B,H,N,KD]
__device__ float g_K[(size_t)CB * CH * CN * CKD];
__device__ float g_V[(size_t)CB * CH * CN * CKD];
__device__ float g_ctx[(size_t)CM * CD];            // [B,N,H*KD]

// ---------------------------------------------------------------------------
// 128x128x8 register-tiled SGEMM core (8x8 microtile, split 4+4 mapping)
// ---------------------------------------------------------------------------

__global__ __launch_bounds__(256, 2) void qkv_gemm_kernel(
    const float* __restrict__ x,
    const float* __restrict__ Wq,
    const float* __restrict__ Wk,
    const float* __restrict__ Wv) {
  const float* W = (blockIdx.z == 0) ? Wq : (blockIdx.z == 1) ? Wk : Wv;
  float* Out = (blockIdx.z == 0) ? g_Q : (blockIdx.z == 1) ? g_K : g_V;

  __shared__ float As[8][128];
  __shared__ float Bs[8][128];
  const int tid = threadIdx.x;
  const int tx = tid & 15;
  const int ty = tid >> 4;
  const int row0 = blockIdx.y * 128;
  const int col0 = blockIdx.x * 128;

  const int arow = tid >> 1;
  const int acol = (tid & 1) * 4;
  const int brow = tid >> 5;
  const int bcol = (tid & 31) * 4;

  const float* Ap = x + (size_t)(row0 + arow) * CD + acol;
  const float* Wp = W + (size_t)brow * CD + col0 + bcol;

  float acc[8][8];
#pragma unroll
  for (int i = 0; i < 8; i++)
#pragma unroll
    for (int j = 0; j < 8; j++) acc[i][j] = 0.f;

  for (int k0 = 0; k0 < CD; k0 += 8) {
    float4 a = *(const float4*)(Ap + k0);
    float4 bv = *(const float4*)(Wp + (size_t)k0 * CD);
    As[acol + 0][arow] = a.x;
    As[acol + 1][arow] = a.y;
    As[acol + 2][arow] = a.z;
    As[acol + 3][arow] = a.w;
    *(float4*)&Bs[brow][bcol] = bv;
    __syncthreads();
#pragma unroll
    for (int k = 0; k < 8; k++) {
      float4 a0 = *(const float4*)&As[k][ty * 4];
      float4 a1 = *(const float4*)&As[k][64 + ty * 4];
      float4 b0 = *(const float4*)&Bs[k][tx * 4];
      float4 b1 = *(const float4*)&Bs[k][64 + tx * 4];
      float ra[8] = {a0.x, a0.y, a0.z, a0.w, a1.x, a1.y, a1.z, a1.w};
      float rb[8] = {b0.x, b0.y, b0.z, b0.w, b1.x, b1.y, b1.z, b1.w};
#pragma unroll
      for (int i = 0; i < 8; i++)
#pragma unroll
        for (int j = 0; j < 8; j++) acc[i][j] = fmaf(ra[i], rb[j], acc[i][j]);
    }
    __syncthreads();
  }

  // Epilogue: scatter into split-head layout [B,H,N,KD]
#pragma unroll
  for (int i = 0; i < 8; i++) {
    int r = row0 + ((i < 4) ? (ty * 4 + i) : (64 + ty * 4 + i - 4));
    int bb = r >> 10;
    int n = r & 1023;
#pragma unroll
    for (int jh = 0; jh < 2; jh++) {
      int c = col0 + ((jh == 0) ? (tx * 4) : (64 + tx * 4));
      int h = c >> 6;
      int d = c & 63;
      float4 v = make_float4(acc[i][jh * 4 + 0], acc[i][jh * 4 + 1],
                             acc[i][jh * 4 + 2], acc[i][jh * 4 + 3]);
      *(float4*)(Out + ((((size_t)bb * CH + h) * CN + n) * CKD + d)) = v;
    }
  }
}

__global__ __launch_bounds__(256, 2) void out_gemm_kernel(
    const float* __restrict__ Wo, float* __restrict__ out) {
  __shared__ float As[8][128];
  __shared__ float Bs[8][128];
  const int tid = threadIdx.x;
  const int tx = tid & 15;
  const int ty = tid >> 4;
  const int row0 = blockIdx.y * 128;
  const int col0 = blockIdx.x * 128;

  const int arow = tid >> 1;
  const int acol = (tid & 1) * 4;
  const int brow = tid >> 5;
  const int bcol = (tid & 31) * 4;

  const float* Ap = g_ctx + (size_t)(row0 + arow) * CD + acol;
  const float* Wp = Wo + (size_t)brow * CD + col0 + bcol;

  float acc[8][8];
#pragma unroll
  for (int i = 0; i < 8; i++)
#pragma unroll
    for (int j = 0; j < 8; j++) acc[i][j] = 0.f;

  for (int k0 = 0; k0 < CD; k0 += 8) {
    float4 a = *(const float4*)(Ap + k0);
    float4 bv = *(const float4*)(Wp + (size_t)k0 * CD);
    As[acol + 0][arow] = a.x;
    As[acol + 1][arow] = a.y;
    As[acol + 2][arow] = a.z;
    As[acol + 3][arow] = a.w;
    *(float4*)&Bs[brow][bcol] = bv;
    __syncthreads();
#pragma unroll
    for (int k = 0; k < 8; k++) {
      float4 a0 = *(const float4*)&As[k][ty * 4];
      float4 a1 = *(const float4*)&As[k][64 + ty * 4];
      float4 b0 = *(const float4*)&Bs[k][tx * 4];
      float4 b1 = *(const float4*)&Bs[k][64 + tx * 4];
      float ra[8] = {a0.x, a0.y, a0.z, a0.w, a1.x, a1.y, a1.z, a1.w};
      float rb[8] = {b0.x, b0.y, b0.z, b0.w, b1.x, b1.y, b1.z, b1.w};
#pragma unroll
      for (int i = 0; i < 8; i++)
#pragma unroll
        for (int j = 0; j < 8; j++) acc[i][j] = fmaf(ra[i], rb[j], acc[i][j]);
    }
    __syncthreads();
  }

#pragma unroll
  for (int i = 0; i < 8; i++) {
    int r = row0 + ((i < 4) ? (ty * 4 + i) : (64 + ty * 4 + i - 4));
#pragma unroll
    for (int jh = 0; jh < 2; jh++) {
      int c = col0 + ((jh == 0) ? (tx * 4) : (64 + tx * 4));
      float4 v = make_float4(acc[i][jh * 4 + 0], acc[i][jh * 4 + 1],
                             acc[i][jh * 4 + 2], acc[i][jh * 4 + 3]);
      *(float4*)(out + (size_t)r * CD + c) = v;
    }
  }
}

// ---------------------------------------------------------------------------
// Flash attention: 1 CTA = (b, h, 64-row Q block); BC=64 K/V tiles
// 256 threads, thread (tr,tc) owns S/O rows tr*4..+3, cols tc*4..+3
// ---------------------------------------------------------------------------

__global__ __launch_bounds__(256) void attn_kernel(
    const float* __restrict__ bias, const float* __restrict__ bias_scale) {
  __shared__ float Qt[4096];    // Q^T: [d][r], Q prescaled by 1/8
  __shared__ float KtPs[4096];  // first K^T [d][c], then reused as P [r][c]
  __shared__ float Vs[4096];    // V [c][d]

  const int qb = blockIdx.x;
  const int h = blockIdx.y;
  const int b = blockIdx.z;
  const int tid = threadIdx.x;
  const int tc = tid & 15;
  const int tr = tid >> 4;

  const float bscale = bias_scale[h];
  const float* Qg = g_Q + (((size_t)b * CH + h) * CN + (size_t)qb * 64) * CKD;
  const float* Kg = g_K + ((size_t)b * CH + h) * CN * CKD;
  const float* Vg = g_V + ((size_t)b * CH + h) * CN * CKD;

  for (int idx = tid; idx < 4096; idx += 256) {
    int r = idx >> 6, d = idx & 63;
    Qt[d * 64 + r] = Qg[idx] * 0.125f;  // SCALE = 1/sqrt(64)
  }

  float m_i[4], l_i[4], o[4][4];
#pragma unroll
  for (int i = 0; i < 4; i++) {
    m_i[i] = -1e30f;
    l_i[i] = 0.f;
#pragma unroll
    for (int j = 0; j < 4; j++) o[i][j] = 0.f;
  }

  for (int kb = 0; kb < 16; kb++) {
    __syncthreads();  // previous-iter P/V consumers done (also covers Qt load)
    for (int idx = tid; idx < 4096; idx += 256) {
      int c = idx >> 6, d = idx & 63;
      float kval = Kg[(size_t)kb * 4096 + idx];
      KtPs[d * 64 + c] = kval;
      Vs[idx] = Vg[(size_t)kb * 4096 + idx];
    }
    __syncthreads();

    // S = (Q*scale) K^T
    float acc[4][4];
#pragma unroll
    for (int i = 0; i < 4; i++)
#pragma unroll
      for (int j = 0; j < 4; j++) acc[i][j] = 0.f;

#pragma unroll 8
    for (int d = 0; d < 64; d++) {
      float4 qv = *(const float4*)&Qt[d * 64 + tr * 4];
      float4 kv = *(const float4*)&KtPs[d * 64 + tc * 4];
      float rq[4] = {qv.x, qv.y, qv.z, qv.w};
      float rk[4] = {kv.x, kv.y, kv.z, kv.w};
#pragma unroll
      for (int i = 0; i < 4; i++)
#pragma unroll
        for (int j = 0; j < 4; j++) acc[i][j] = fmaf(rq[i], rk[j], acc[i][j]);
    }

    // bias + online softmax (row reduction over 16-lane groups)
    const float* bp = bias + (size_t)(qb * 64) * CN + (size_t)kb * 64;
#pragma unroll
    for (int i = 0; i < 4; i++) {
      float4 bv = *(const float4*)(bp + (size_t)(tr * 4 + i) * CN + tc * 4);
      acc[i][0] = fmaf(bv.x, bscale, acc[i][0]);
      acc[i][1] = fmaf(bv.y, bscale, acc[i][1]);
      acc[i][2] = fmaf(bv.z, bscale, acc[i][2]);
      acc[i][3] = fmaf(bv.w, bscale, acc[i][3]);

      float mx = fmaxf(fmaxf(acc[i][0], acc[i][1]), fmaxf(acc[i][2], acc[i][3]));
#pragma unroll
      for (int off = 8; off >= 1; off >>= 1)
        mx = fmaxf(mx, __shfl_xor_sync(0xffffffffu, mx, off));
      float mnew = fmaxf(m_i[i], mx);
      float corr = __expf(m_i[i] - mnew);
      m_i[i] = mnew;

      float sum = 0.f;
#pragma unroll
      for (int j = 0; j < 4; j++) {
        float p = __expf(acc[i][j] - mnew);
        acc[i][j] = p;
        sum += p;
      }
#pragma unroll
      for (int off = 8; off >= 1; off >>= 1)
        sum += __shfl_xor_sync(0xffffffffu, sum, off);
      l_i[i] = l_i[i] * corr + sum;
#pragma unroll
      for (int j = 0; j < 4; j++) o[i][j] *= corr;
    }

    __syncthreads();  // all S reads of KtPs done before overwriting with P
#pragma unroll
    for (int i = 0; i < 4; i++)
      *(float4*)&KtPs[(tr * 4 + i) * 64 + tc * 4] =
          make_float4(acc[i][0], acc[i][1], acc[i][2], acc[i][3]);
    __syncthreads();

    // O += P V
#pragma unroll 4
    for (int c4 = 0; c4 < 16; c4++) {
      float4 vv0 = *(const float4*)&Vs[(c4 * 4 + 0) * 64 + tc * 4];
      float4 vv1 = *(const float4*)&Vs[(c4 * 4 + 1) * 64 + tc * 4];
      float4 vv2 = *(const float4*)&Vs[(c4 * 4 + 2) * 64 + tc * 4];
      float4 vv3 = *(const float4*)&Vs[(c4 * 4 + 3) * 64 + tc * 4];
#pragma unroll
      for (int i = 0; i < 4; i++) {
        float4 pv = *(const float4*)&KtPs[(tr * 4 + i) * 64 + c4 * 4];
        o[i][0] += pv.x * vv0.x + pv.y * vv1.x + pv.z * vv2.x + pv.w * vv3.x;
        o[i][1] += pv.x * vv0.y + pv.y * vv1.y + pv.z * vv2.y + pv.w * vv3.y;
        o[i][2] += pv.x * vv0.z + pv.y * vv1.z + pv.z * vv2.z + pv.w * vv3.z;
        o[i][3] += pv.x * vv0.w + pv.y * vv1.w + pv.z * vv2.w + pv.w * vv3.w;
      }
    }
  }

  // ctx[b][n][h*64+d] = O / l
  float* cp = g_ctx + ((size_t)b * CN + (size_t)qb * 64) * CD + h * CKD;
#pragma unroll
  for (int i = 0; i < 4; i++) {
    float inv = 1.f / l_i[i];
    float4 v = make_float4(o[i][0] * inv, o[i][1] * inv, o[i][2] * inv, o[i][3] * inv);
    *(float4*)(cp + (size_t)(tr * 4 + i) * CD + tc * 4) = v;
  }
}

// ---------------------------------------------------------------------------

extern "C" void kernel_launch(void* const* d_in, const int* in_sizes, int n_in,
                              void* d_out, int out_size) {
  const float* x = (const float*)d_in[0];
  const float* leadlag_bias = (const float*)d_in[1];
  const float* Wq = (const float*)d_in[2];
  const float* Wk = (const float*)d_in[3];
  const float* Wv = (const float*)d_in[4];
  const float* Wo = (const float*)d_in[5];
  const float* bias_scale = (const float*)d_in[6];
  float* out = (float*)d_out;

  (void)in_sizes; (void)n_in; (void)out_size;

  // Q/K/V projections: [16384,512] @ [512,512] x3, scatter to [B,H,N,KD]
  qkv_gemm_kernel<<<dim3(CD / 128, CM / 128, 3), 256>>>(x, Wq, Wk, Wv);
  // Flash attention per (qblock, head, batch)
  attn_kernel<<<dim3(CN / 64, CH, CB), 256>>>(leadlag_bias, bias_scale);
  // Output projection: [16384,512] @ [512,512] -> d_out
  out_gemm_kernel<<<dim3(CD / 128, CM / 128), 256>>>(Wo, out);
}

// round 3
// speedup vs baseline: 1.2703x; 1.2703x over previous
#include <cuda_runtime.h>
#include <cstdint>

#define CB 16
#define CN 1024
#define CD 512
#define CH 8
#define CKD 64
#define CM (CB * CN)  // 16384

// Scratch (alloc-free rule: __device__ globals)
__device__ float g_Q[(size_t)CB * CH * CN * CKD];   // [B,H,N,KD]
__device__ float g_K[(size_t)CB * CH * CN * CKD];
__device__ float g_V[(size_t)CB * CH * CN * CKD];
__device__ float g_ctx[(size_t)CM * CD];            // [B,N,H*KD]
__device__ float g_Wt[4 * CD * CD];                 // transposed weights [n][k]

// ---------------------------------------------------------------------------
// Helpers
// ---------------------------------------------------------------------------

__device__ __forceinline__ float tf32_rna(float x) {
  uint32_t r;
  asm("cvt.rna.tf32.f32 %0, %1;" : "=r"(r) : "f"(x));
  return __uint_as_float(r);
}

__device__ __forceinline__ void mma_16n8k8(float* c, const uint32_t* a,
                                           const uint32_t* b) {
  asm volatile(
      "mma.sync.aligned.m16n8k8.row.col.f32.tf32.tf32.f32 "
      "{%0,%1,%2,%3}, {%4,%5,%6,%7}, {%8,%9}, {%0,%1,%2,%3};"
      : "+f"(c[0]), "+f"(c[1]), "+f"(c[2]), "+f"(c[3])
      : "r"(a[0]), "r"(a[1]), "r"(a[2]), "r"(a[3]), "r"(b[0]), "r"(b[1]));
}

// ---------------------------------------------------------------------------
// Weight transpose: Wt[n][k] = W[k][n]  (4 matrices, 512x512)
// ---------------------------------------------------------------------------

__global__ void transpose_w_kernel(const float* __restrict__ Wq,
                                   const float* __restrict__ Wk,
                                   const float* __restrict__ Wv,
                                   const float* __restrict__ Wo) {
  __shared__ float t[32][33];
  const float* W = (blockIdx.z == 0) ? Wq : (blockIdx.z == 1) ? Wk
                   : (blockIdx.z == 2) ? Wv : Wo;
  float* Out = g_Wt + (size_t)blockIdx.z * CD * CD;
  int n0 = blockIdx.x * 32, k0 = blockIdx.y * 32;
  int tx = threadIdx.x, ty = threadIdx.y;
#pragma unroll
  for (int s = 0; s < 4; s++)
    t[ty + s * 8][tx] = W[(size_t)(k0 + ty + s * 8) * CD + n0 + tx];
  __syncthreads();
#pragma unroll
  for (int s = 0; s < 4; s++)
    Out[(size_t)(n0 + ty + s * 8) * CD + k0 + tx] = t[tx][ty + s * 8];
}

// ---------------------------------------------------------------------------
// tf32 mma.sync GEMM: C[16384, 512] = A[M,512] * Bt[n][k]^T
// CTA 128x128, 8 warps (4x2), warp tile 32x64, BK=16 double-buffered.
// Smem stride 20 floats -> conflict-free (g,tg) fragment loads.
// ---------------------------------------------------------------------------

#define BK 16
#define LDSROW 20

__device__ __forceinline__ void gemm_mma_tile(const float* __restrict__ A,
                                              const float* __restrict__ Bt,
                                              float* __restrict__ Out,
                                              int mode) {
  __shared__ float As[2][128 * LDSROW];
  __shared__ float Bs[2][128 * LDSROW];

  const int tid = threadIdx.x;
  const int lane = tid & 31;
  const int warp = tid >> 5;
  const int wm = warp & 3;   // 0..3 -> rows wm*32
  const int wn = warp >> 2;  // 0..1 -> cols wn*64
  const int g = lane >> 2;
  const int tg = lane & 3;

  const int col0 = blockIdx.x * 128;
  const int row0 = blockIdx.y * 128;

  const int lr = tid >> 2;        // 0..63 (row within tile, +64 for 2nd)
  const int lc = (tid & 3) * 4;   // float col within BK chunk

  float acc[2][8][4];
#pragma unroll
  for (int mt = 0; mt < 2; mt++)
#pragma unroll
    for (int nt = 0; nt < 8; nt++)
#pragma unroll
      for (int i = 0; i < 4; i++) acc[mt][nt][i] = 0.f;

  float4 ra0, ra1, rb0, rb1;
  {
    const float* ap = A + (size_t)(row0 + lr) * CD + lc;
    const float* bp = Bt + (size_t)(col0 + lr) * CD + lc;
    ra0 = *(const float4*)ap;
    ra1 = *(const float4*)(ap + (size_t)64 * CD);
    rb0 = *(const float4*)bp;
    rb1 = *(const float4*)(bp + (size_t)64 * CD);
  }

  for (int kt = 0; kt < CD / BK; kt++) {
    const int buf = kt & 1;
    float* as = As[buf];
    float* bs = Bs[buf];
    // store (with tf32 rounding)
    {
      int o0 = lr * LDSROW + lc;
      int o1 = (lr + 64) * LDSROW + lc;
      as[o0 + 0] = tf32_rna(ra0.x); as[o0 + 1] = tf32_rna(ra0.y);
      as[o0 + 2] = tf32_rna(ra0.z); as[o0 + 3] = tf32_rna(ra0.w);
      as[o1 + 0] = tf32_rna(ra1.x); as[o1 + 1] = tf32_rna(ra1.y);
      as[o1 + 2] = tf32_rna(ra1.z); as[o1 + 3] = tf32_rna(ra1.w);
      bs[o0 + 0] = tf32_rna(rb0.x); bs[o0 + 1] = tf32_rna(rb0.y);
      bs[o0 + 2] = tf32_rna(rb0.z); bs[o0 + 3] = tf32_rna(rb0.w);
      bs[o1 + 0] = tf32_rna(rb1.x); bs[o1 + 1] = tf32_rna(rb1.y);
      bs[o1 + 2] = tf32_rna(rb1.z); bs[o1 + 3] = tf32_rna(rb1.w);
    }
    __syncthreads();

    if (kt + 1 < CD / BK) {
      int k0 = (kt + 1) * BK;
      const float* ap = A + (size_t)(row0 + lr) * CD + k0 + lc;
      const float* bp = Bt + (size_t)(col0 + lr) * CD + k0 + lc;
      ra0 = *(const float4*)ap;
      ra1 = *(const float4*)(ap + (size_t)64 * CD);
      rb0 = *(const float4*)bp;
      rb1 = *(const float4*)(bp + (size_t)64 * CD);
    }

    const uint32_t* asu = (const uint32_t*)as;
    const uint32_t* bsu = (const uint32_t*)bs;
#pragma unroll
    for (int k8 = 0; k8 < 2; k8++) {
      const int kb = k8 * 8 + tg;
      uint32_t af[2][4];
#pragma unroll
      for (int mt = 0; mt < 2; mt++) {
        int r = wm * 32 + mt * 16 + g;
        af[mt][0] = asu[r * LDSROW + kb];
        af[mt][1] = asu[(r + 8) * LDSROW + kb];
        af[mt][2] = asu[r * LDSROW + kb + 4];
        af[mt][3] = asu[(r + 8) * LDSROW + kb + 4];
      }
#pragma unroll
      for (int nt = 0; nt < 8; nt++) {
        int n = wn * 64 + nt * 8 + g;
        uint32_t bf[2];
        bf[0] = bsu[n * LDSROW + kb];
        bf[1] = bsu[n * LDSROW + kb + 4];
        mma_16n8k8(acc[0][nt], af[0], bf);
        mma_16n8k8(acc[1][nt], af[1], bf);
      }
    }
    __syncthreads();
  }

  // Epilogue: direct float2 stores from fragment layout
#pragma unroll
  for (int mt = 0; mt < 2; mt++) {
#pragma unroll
    for (int nt = 0; nt < 8; nt++) {
      int R = row0 + wm * 32 + mt * 16 + g;
      int C = col0 + wn * 64 + nt * 8 + 2 * tg;
      float2 v0 = make_float2(acc[mt][nt][0], acc[mt][nt][1]);
      float2 v1 = make_float2(acc[mt][nt][2], acc[mt][nt][3]);
      if (mode == 0) {
        int h = C >> 6, d = C & 63;
        int bb0 = R >> 10, n0 = R & 1023;
        int bb1 = (R + 8) >> 10, n1 = (R + 8) & 1023;
        *(float2*)(Out + ((((size_t)bb0 * CH + h) * CN + n0) * CKD + d)) = v0;
        *(float2*)(Out + ((((size_t)bb1 * CH + h) * CN + n1) * CKD + d)) = v1;
      } else {
        *(float2*)(Out + (size_t)R * CD + C) = v0;
        *(float2*)(Out + (size_t)(R + 8) * CD + C) = v1;
      }
    }
  }
}

__global__ __launch_bounds__(256) void qkv_mma_kernel(const float* __restrict__ x) {
  const float* Bt = g_Wt + (size_t)blockIdx.z * CD * CD;
  float* Out = (blockIdx.z == 0) ? g_Q : (blockIdx.z == 1) ? g_K : g_V;
  gemm_mma_tile(x, Bt, Out, 0);
}

__global__ __launch_bounds__(256) void out_mma_kernel(float* __restrict__ out) {
  gemm_mma_tile(g_ctx, g_Wt + (size_t)3 * CD * CD, out, 1);
}

// ---------------------------------------------------------------------------
// Flash attention (unchanged, known-good): 1 CTA = (b, h, 64-row Q block)
// ---------------------------------------------------------------------------

__global__ __launch_bounds__(256) void attn_kernel(
    const float* __restrict__ bias, const float* __restrict__ bias_scale) {
  __shared__ float Qt[4096];
  __shared__ float KtPs[4096];
  __shared__ float Vs[4096];

  const int qb = blockIdx.x;
  const int h = blockIdx.y;
  const int b = blockIdx.z;
  const int tid = threadIdx.x;
  const int tc = tid & 15;
  const int tr = tid >> 4;

  const float bscale = bias_scale[h];
  const float* Qg = g_Q + (((size_t)b * CH + h) * CN + (size_t)qb * 64) * CKD;
  const float* Kg = g_K + ((size_t)b * CH + h) * CN * CKD;
  const float* Vg = g_V + ((size_t)b * CH + h) * CN * CKD;

  for (int idx = tid; idx < 4096; idx += 256) {
    int r = idx >> 6, d = idx & 63;
    Qt[d * 64 + r] = Qg[idx] * 0.125f;
  }

  float m_i[4], l_i[4], o[4][4];
#pragma unroll
  for (int i = 0; i < 4; i++) {
    m_i[i] = -1e30f;
    l_i[i] = 0.f;
#pragma unroll
    for (int j = 0; j < 4; j++) o[i][j] = 0.f;
  }

  for (int kb = 0; kb < 16; kb++) {
    __syncthreads();
    for (int idx = tid; idx < 4096; idx += 256) {
      int c = idx >> 6, d = idx & 63;
      float kval = Kg[(size_t)kb * 4096 + idx];
      KtPs[d * 64 + c] = kval;
      Vs[idx] = Vg[(size_t)kb * 4096 + idx];
    }
    __syncthreads();

    float acc[4][4];
#pragma unroll
    for (int i = 0; i < 4; i++)
#pragma unroll
      for (int j = 0; j < 4; j++) acc[i][j] = 0.f;

#pragma unroll 8
    for (int d = 0; d < 64; d++) {
      float4 qv = *(const float4*)&Qt[d * 64 + tr * 4];
      float4 kv = *(const float4*)&KtPs[d * 64 + tc * 4];
      float rq[4] = {qv.x, qv.y, qv.z, qv.w};
      float rk[4] = {kv.x, kv.y, kv.z, kv.w};
#pragma unroll
      for (int i = 0; i < 4; i++)
#pragma unroll
        for (int j = 0; j < 4; j++) acc[i][j] = fmaf(rq[i], rk[j], acc[i][j]);
    }

    const float* bp = bias + (size_t)(qb * 64) * CN + (size_t)kb * 64;
#pragma unroll
    for (int i = 0; i < 4; i++) {
      float4 bv = *(const float4*)(bp + (size_t)(tr * 4 + i) * CN + tc * 4);
      acc[i][0] = fmaf(bv.x, bscale, acc[i][0]);
      acc[i][1] = fmaf(bv.y, bscale, acc[i][1]);
      acc[i][2] = fmaf(bv.z, bscale, acc[i][2]);
      acc[i][3] = fmaf(bv.w, bscale, acc[i][3]);

      float mx = fmaxf(fmaxf(acc[i][0], acc[i][1]), fmaxf(acc[i][2], acc[i][3]));
#pragma unroll
      for (int off = 8; off >= 1; off >>= 1)
        mx = fmaxf(mx, __shfl_xor_sync(0xffffffffu, mx, off));
      float mnew = fmaxf(m_i[i], mx);
      float corr = __expf(m_i[i] - mnew);
      m_i[i] = mnew;

      float sum = 0.f;
#pragma unroll
      for (int j = 0; j < 4; j++) {
        float p = __expf(acc[i][j] - mnew);
        acc[i][j] = p;
        sum += p;
      }
#pragma unroll
      for (int off = 8; off >= 1; off >>= 1)
        sum += __shfl_xor_sync(0xffffffffu, sum, off);
      l_i[i] = l_i[i] * corr + sum;
#pragma unroll
      for (int j = 0; j < 4; j++) o[i][j] *= corr;
    }

    __syncthreads();
#pragma unroll
    for (int i = 0; i < 4; i++)
      *(float4*)&KtPs[(tr * 4 + i) * 64 + tc * 4] =
          make_float4(acc[i][0], acc[i][1], acc[i][2], acc[i][3]);
    __syncthreads();

#pragma unroll 4
    for (int c4 = 0; c4 < 16; c4++) {
      float4 vv0 = *(const float4*)&Vs[(c4 * 4 + 0) * 64 + tc * 4];
      float4 vv1 = *(const float4*)&Vs[(c4 * 4 + 1) * 64 + tc * 4];
      float4 vv2 = *(const float4*)&Vs[(c4 * 4 + 2) * 64 + tc * 4];
      float4 vv3 = *(const float4*)&Vs[(c4 * 4 + 3) * 64 + tc * 4];
#pragma unroll
      for (int i = 0; i < 4; i++) {
        float4 pv = *(const float4*)&KtPs[(tr * 4 + i) * 64 + c4 * 4];
        o[i][0] += pv.x * vv0.x + pv.y * vv1.x + pv.z * vv2.x + pv.w * vv3.x;
        o[i][1] += pv.x * vv0.y + pv.y * vv1.y + pv.z * vv2.y + pv.w * vv3.y;
        o[i][2] += pv.x * vv0.z + pv.y * vv1.z + pv.z * vv2.z + pv.w * vv3.z;
        o[i][3] += pv.x * vv0.w + pv.y * vv1.w + pv.z * vv2.w + pv.w * vv3.w;
      }
    }
  }

  float* cp = g_ctx + ((size_t)b * CN + (size_t)qb * 64) * CD + h * CKD;
#pragma unroll
  for (int i = 0; i < 4; i++) {
    float inv = 1.f / l_i[i];
    float4 v = make_float4(o[i][0] * inv, o[i][1] * inv, o[i][2] * inv, o[i][3] * inv);
    *(float4*)(cp + (size_t)(tr * 4 + i) * CD + tc * 4) = v;
  }
}

// ---------------------------------------------------------------------------

extern "C" void kernel_launch(void* const* d_in, const int* in_sizes, int n_in,
                              void* d_out, int out_size) {
  const float* x = (const float*)d_in[0];
  const float* leadlag_bias = (const float*)d_in[1];
  const float* Wq = (const float*)d_in[2];
  const float* Wk = (const float*)d_in[3];
  const float* Wv = (const float*)d_in[4];
  const float* Wo = (const float*)d_in[5];
  const float* bias_scale = (const float*)d_in[6];
  float* out = (float*)d_out;

  (void)in_sizes; (void)n_in; (void)out_size;

  // Transpose all weights into K-major Wt
  transpose_w_kernel<<<dim3(CD / 32, CD / 32, 4), dim3(32, 8)>>>(Wq, Wk, Wv, Wo);
  // QKV projections (tf32 mma.sync), scatter to [B,H,N,KD]
  qkv_mma_kernel<<<dim3(CD / 128, CM / 128, 3), 256>>>(x);
  // Flash attention per (qblock, head, batch)
  attn_kernel<<<dim3(CN / 64, CH, CB), 256>>>(leadlag_bias, bias_scale);
  // Output projection (tf32 mma.sync) -> d_out
  out_mma_kernel<<<dim3(CD / 128, CM / 128, 1), 256>>>(out);
}

// round 4
// speedup vs baseline: 1.5681x; 1.2344x over previous
#include <cuda_runtime.h>
#include <cstdint>

#define CB 16
#define CN 1024
#define CD 512
#define CH 8
#define CKD 64
#define CM (CB * CN)  // 16384

// Scratch (alloc-free rule: __device__ globals)
__device__ float g_Q[(size_t)CB * CH * CN * CKD];   // [B,H,N,KD]
__device__ float g_K[(size_t)CB * CH * CN * CKD];
__device__ float g_V[(size_t)CB * CH * CN * CKD];
__device__ float g_ctx[(size_t)CM * CD];            // [B,N,H*KD]
__device__ float g_Wt[4 * CD * CD];                 // transposed weights [n][k]

// ---------------------------------------------------------------------------
// Helpers
// ---------------------------------------------------------------------------

__device__ __forceinline__ float tf32_rna(float x) {
  uint32_t r;
  asm("cvt.rna.tf32.f32 %0, %1;" : "=r"(r) : "f"(x));
  return __uint_as_float(r);
}

__device__ __forceinline__ void mma_16n8k8(float* c, const uint32_t* a,
                                           const uint32_t* b) {
  asm volatile(
      "mma.sync.aligned.m16n8k8.row.col.f32.tf32.tf32.f32 "
      "{%0,%1,%2,%3}, {%4,%5,%6,%7}, {%8,%9}, {%0,%1,%2,%3};"
      : "+f"(c[0]), "+f"(c[1]), "+f"(c[2]), "+f"(c[3])
      : "r"(a[0]), "r"(a[1]), "r"(a[2]), "r"(a[3]), "r"(b[0]), "r"(b[1]));
}

__device__ __forceinline__ void cp16(float* dst, const float* src) {
  uint32_t d = (uint32_t)__cvta_generic_to_shared(dst);
  asm volatile("cp.async.cg.shared.global [%0], [%1], 16;" ::"r"(d), "l"(src)
               : "memory");
}
#define CP_COMMIT() asm volatile("cp.async.commit_group;" ::: "memory")
#define CP_WAIT(n) asm volatile("cp.async.wait_group %0;" ::"n"(n) : "memory")

// ---------------------------------------------------------------------------
// Weight transpose: Wt[n][k] = W[k][n]  (4 matrices, 512x512)
// ---------------------------------------------------------------------------

__global__ void transpose_w_kernel(const float* __restrict__ Wq,
                                   const float* __restrict__ Wk,
                                   const float* __restrict__ Wv,
                                   const float* __restrict__ Wo) {
  __shared__ float t[32][33];
  const float* W = (blockIdx.z == 0) ? Wq : (blockIdx.z == 1) ? Wk
                   : (blockIdx.z == 2) ? Wv : Wo;
  float* Out = g_Wt + (size_t)blockIdx.z * CD * CD;
  int n0 = blockIdx.x * 32, k0 = blockIdx.y * 32;
  int tx = threadIdx.x, ty = threadIdx.y;
#pragma unroll
  for (int s = 0; s < 4; s++)
    t[ty + s * 8][tx] = W[(size_t)(k0 + ty + s * 8) * CD + n0 + tx];
  __syncthreads();
#pragma unroll
  for (int s = 0; s < 4; s++)
    Out[(size_t)(n0 + ty + s * 8) * CD + k0 + tx] = t[tx][ty + s * 8];
}

// ---------------------------------------------------------------------------
// tf32 mma.sync GEMM (unchanged from R3): C[16384,512] = A * Bt^T
// ---------------------------------------------------------------------------

#define BK 16
#define LDSROW 20

__device__ __forceinline__ void gemm_mma_tile(const float* __restrict__ A,
                                              const float* __restrict__ Bt,
                                              float* __restrict__ Out,
                                              int mode) {
  __shared__ float As[2][128 * LDSROW];
  __shared__ float Bs[2][128 * LDSROW];

  const int tid = threadIdx.x;
  const int lane = tid & 31;
  const int warp = tid >> 5;
  const int wm = warp & 3;
  const int wn = warp >> 2;
  const int g = lane >> 2;
  const int tg = lane & 3;

  const int col0 = blockIdx.x * 128;
  const int row0 = blockIdx.y * 128;

  const int lr = tid >> 2;
  const int lc = (tid & 3) * 4;

  float acc[2][8][4];
#pragma unroll
  for (int mt = 0; mt < 2; mt++)
#pragma unroll
    for (int nt = 0; nt < 8; nt++)
#pragma unroll
      for (int i = 0; i < 4; i++) acc[mt][nt][i] = 0.f;

  float4 ra0, ra1, rb0, rb1;
  {
    const float* ap = A + (size_t)(row0 + lr) * CD + lc;
    const float* bp = Bt + (size_t)(col0 + lr) * CD + lc;
    ra0 = *(const float4*)ap;
    ra1 = *(const float4*)(ap + (size_t)64 * CD);
    rb0 = *(const float4*)bp;
    rb1 = *(const float4*)(bp + (size_t)64 * CD);
  }

  for (int kt = 0; kt < CD / BK; kt++) {
    const int buf = kt & 1;
    float* as = As[buf];
    float* bs = Bs[buf];
    {
      int o0 = lr * LDSROW + lc;
      int o1 = (lr + 64) * LDSROW + lc;
      as[o0 + 0] = tf32_rna(ra0.x); as[o0 + 1] = tf32_rna(ra0.y);
      as[o0 + 2] = tf32_rna(ra0.z); as[o0 + 3] = tf32_rna(ra0.w);
      as[o1 + 0] = tf32_rna(ra1.x); as[o1 + 1] = tf32_rna(ra1.y);
      as[o1 + 2] = tf32_rna(ra1.z); as[o1 + 3] = tf32_rna(ra1.w);
      bs[o0 + 0] = tf32_rna(rb0.x); bs[o0 + 1] = tf32_rna(rb0.y);
      bs[o0 + 2] = tf32_rna(rb0.z); bs[o0 + 3] = tf32_rna(rb0.w);
      bs[o1 + 0] = tf32_rna(rb1.x); bs[o1 + 1] = tf32_rna(rb1.y);
      bs[o1 + 2] = tf32_rna(rb1.z); bs[o1 + 3] = tf32_rna(rb1.w);
    }
    __syncthreads();

    if (kt + 1 < CD / BK) {
      int k0 = (kt + 1) * BK;
      const float* ap = A + (size_t)(row0 + lr) * CD + k0 + lc;
      const float* bp = Bt + (size_t)(col0 + lr) * CD + k0 + lc;
      ra0 = *(const float4*)ap;
      ra1 = *(const float4*)(ap + (size_t)64 * CD);
      rb0 = *(const float4*)bp;
      rb1 = *(const float4*)(bp + (size_t)64 * CD);
    }

    const uint32_t* asu = (const uint32_t*)as;
    const uint32_t* bsu = (const uint32_t*)bs;
#pragma unroll
    for (int k8 = 0; k8 < 2; k8++) {
      const int kb = k8 * 8 + tg;
      uint32_t af[2][4];
#pragma unroll
      for (int mt = 0; mt < 2; mt++) {
        int r = wm * 32 + mt * 16 + g;
        af[mt][0] = asu[r * LDSROW + kb];
        af[mt][1] = asu[(r + 8) * LDSROW + kb];
        af[mt][2] = asu[r * LDSROW + kb + 4];
        af[mt][3] = asu[(r + 8) * LDSROW + kb + 4];
      }
#pragma unroll
      for (int nt = 0; nt < 8; nt++) {
        int n = wn * 64 + nt * 8 + g;
        uint32_t bf[2];
        bf[0] = bsu[n * LDSROW + kb];
        bf[1] = bsu[n * LDSROW + kb + 4];
        mma_16n8k8(acc[0][nt], af[0], bf);
        mma_16n8k8(acc[1][nt], af[1], bf);
      }
    }
    __syncthreads();
  }

#pragma unroll
  for (int mt = 0; mt < 2; mt++) {
#pragma unroll
    for (int nt = 0; nt < 8; nt++) {
      int R = row0 + wm * 32 + mt * 16 + g;
      int C = col0 + wn * 64 + nt * 8 + 2 * tg;
      float2 v0 = make_float2(acc[mt][nt][0], acc[mt][nt][1]);
      float2 v1 = make_float2(acc[mt][nt][2], acc[mt][nt][3]);
      if (mode == 0) {
        int h = C >> 6, d = C & 63;
        int bb0 = R >> 10, n0 = R & 1023;
        int bb1 = (R + 8) >> 10, n1 = (R + 8) & 1023;
        *(float2*)(Out + ((((size_t)bb0 * CH + h) * CN + n0) * CKD + d)) = v0;
        *(float2*)(Out + ((((size_t)bb1 * CH + h) * CN + n1) * CKD + d)) = v1;
      } else {
        *(float2*)(Out + (size_t)R * CD + C) = v0;
        *(float2*)(Out + (size_t)(R + 8) * CD + C) = v1;
      }
    }
  }
}

__global__ __launch_bounds__(256) void qkv_mma_kernel(const float* __restrict__ x) {
  const float* Bt = g_Wt + (size_t)blockIdx.z * CD * CD;
  float* Out = (blockIdx.z == 0) ? g_Q : (blockIdx.z == 1) ? g_K : g_V;
  gemm_mma_tile(x, Bt, Out, 0);
}

__global__ __launch_bounds__(256) void out_mma_kernel(float* __restrict__ out) {
  gemm_mma_tile(g_ctx, g_Wt + (size_t)3 * CD * CD, out, 1);
}

// ---------------------------------------------------------------------------
// mma.sync flash attention: CTA = (qb 128 rows, h, b); 8 warps x m16.
// K/V blocks of 64 cp.async double-buffered, stride 76 (conflict-free both ways).
// ---------------------------------------------------------------------------

#define KVSTRIDE 76
#define KVTILE (64 * KVSTRIDE)          // 4864 floats
#define ATTN_SMEM_FLOATS (4 * KVTILE)   // 19456 floats = 77824 B
#define ATTN_SMEM_BYTES (ATTN_SMEM_FLOATS * 4)

__device__ __forceinline__ void stage_kv(const float* __restrict__ Kg,
                                         const float* __restrict__ Vg,
                                         float* kb_dst, float* vb_dst, int kb,
                                         int tid) {
#pragma unroll
  for (int it = 0; it < 4; it++) {
    int j = tid + it * 256;
    int row = j >> 4;
    int c4 = (j & 15) * 4;
    cp16(kb_dst + row * KVSTRIDE + c4, Kg + (size_t)(kb * 64 + row) * CKD + c4);
    cp16(vb_dst + row * KVSTRIDE + c4, Vg + (size_t)(kb * 64 + row) * CKD + c4);
  }
  CP_COMMIT();
}

__global__ __launch_bounds__(256) void attn_mma_kernel(
    const float* __restrict__ bias, const float* __restrict__ bias_scale) {
  extern __shared__ float sm[];
  float* Kbuf[2] = {sm, sm + 2 * KVTILE};
  float* Vbuf[2] = {sm + KVTILE, sm + 3 * KVTILE};

  const int qb = blockIdx.x;
  const int h = blockIdx.y;
  const int b = blockIdx.z;
  const int tid = threadIdx.x;
  const int lane = tid & 31;
  const int warp = tid >> 5;
  const int g = lane >> 2;
  const int tg = lane & 3;
  const int m0 = warp * 16;

  const float bscale = bias_scale[h];
  const float* Qg = g_Q + (((size_t)b * CH + h) * CN + (size_t)qb * 128) * CKD;
  const float* Kg = g_K + ((size_t)b * CH + h) * CN * CKD;
  const float* Vg = g_V + ((size_t)b * CH + h) * CN * CKD;

  // --- Stage Q (scaled, tf32) into smem, extract fragments to registers ---
#pragma unroll
  for (int it = 0; it < 8; it++) {
    int j = tid + it * 256;
    int row = j >> 4;
    int c4 = (j & 15) * 4;
    float4 v = *(const float4*)(Qg + (size_t)row * CKD + c4);
    sm[row * KVSTRIDE + c4 + 0] = tf32_rna(v.x * 0.125f);
    sm[row * KVSTRIDE + c4 + 1] = tf32_rna(v.y * 0.125f);
    sm[row * KVSTRIDE + c4 + 2] = tf32_rna(v.z * 0.125f);
    sm[row * KVSTRIDE + c4 + 3] = tf32_rna(v.w * 0.125f);
  }
  __syncthreads();

  uint32_t qf[8][4];
  {
    const uint32_t* smu = (const uint32_t*)sm;
#pragma unroll
    for (int j = 0; j < 8; j++) {
      int r0 = (m0 + g) * KVSTRIDE;
      int r1 = (m0 + 8 + g) * KVSTRIDE;
      qf[j][0] = smu[r0 + 8 * j + tg];
      qf[j][1] = smu[r1 + 8 * j + tg];
      qf[j][2] = smu[r0 + 8 * j + tg + 4];
      qf[j][3] = smu[r1 + 8 * j + tg + 4];
    }
  }
  __syncthreads();  // Q reads done before cp.async overwrites region

  float oacc[8][4];
#pragma unroll
  for (int t = 0; t < 8; t++)
#pragma unroll
    for (int c = 0; c < 4; c++) oacc[t][c] = 0.f;
  float m_i[2] = {-1e30f, -1e30f};
  float l_i[2] = {0.f, 0.f};

  stage_kv(Kg, Vg, Kbuf[0], Vbuf[0], 0, tid);

  const int q0 = qb * 128 + m0 + g;

  for (int kb = 0; kb < 16; kb++) {
    const int buf = kb & 1;
    if (kb + 1 < 16)
      stage_kv(Kg, Vg, Kbuf[buf ^ 1], Vbuf[buf ^ 1], kb + 1, tid);

    if (kb + 1 < 16) { CP_WAIT(1); } else { CP_WAIT(0); }
    __syncthreads();

    // In-place tf32 conversion of the 64x64 data region of K and V
    {
      float* kp = Kbuf[buf];
      float* vp = Vbuf[buf];
#pragma unroll
      for (int it = 0; it < 4; it++) {
        int j = tid + it * 256;
        int o = (j >> 4) * KVSTRIDE + (j & 15) * 4;
        float4 kv = *(float4*)(kp + o);
        kv.x = tf32_rna(kv.x); kv.y = tf32_rna(kv.y);
        kv.z = tf32_rna(kv.z); kv.w = tf32_rna(kv.w);
        *(float4*)(kp + o) = kv;
        float4 vv = *(float4*)(vp + o);
        vv.x = tf32_rna(vv.x); vv.y = tf32_rna(vv.y);
        vv.z = tf32_rna(vv.z); vv.w = tf32_rna(vv.w);
        *(float4*)(vp + o) = vv;
      }
    }
    __syncthreads();

    const uint32_t* ksu = (const uint32_t*)Kbuf[buf];
    const uint32_t* vsu = (const uint32_t*)Vbuf[buf];

    // --- S = Q K^T ---
    float sacc[8][4];
#pragma unroll
    for (int t = 0; t < 8; t++)
#pragma unroll
      for (int c = 0; c < 4; c++) sacc[t][c] = 0.f;

#pragma unroll
    for (int j = 0; j < 8; j++) {
#pragma unroll
      for (int t = 0; t < 8; t++) {
        uint32_t bf[2];
        bf[0] = ksu[(t * 8 + g) * KVSTRIDE + 8 * j + tg];
        bf[1] = ksu[(t * 8 + g) * KVSTRIDE + 8 * j + tg + 4];
        mma_16n8k8(sacc[t], qf[j], bf);
      }
    }

    // --- bias + online softmax ---
    const float* bp = bias + (size_t)q0 * CN + kb * 64;
    float mnew0 = -1e30f, mnew1 = -1e30f;
#pragma unroll
    for (int t = 0; t < 8; t++) {
      float2 bv0 = *(const float2*)(bp + t * 8 + 2 * tg);
      float2 bv1 = *(const float2*)(bp + (size_t)8 * CN + t * 8 + 2 * tg);
      sacc[t][0] = fmaf(bv0.x, bscale, sacc[t][0]);
      sacc[t][1] = fmaf(bv0.y, bscale, sacc[t][1]);
      sacc[t][2] = fmaf(bv1.x, bscale, sacc[t][2]);
      sacc[t][3] = fmaf(bv1.y, bscale, sacc[t][3]);
      mnew0 = fmaxf(mnew0, fmaxf(sacc[t][0], sacc[t][1]));
      mnew1 = fmaxf(mnew1, fmaxf(sacc[t][2], sacc[t][3]));
    }
#pragma unroll
    for (int off = 1; off <= 2; off <<= 1) {
      mnew0 = fmaxf(mnew0, __shfl_xor_sync(0xffffffffu, mnew0, off));
      mnew1 = fmaxf(mnew1, __shfl_xor_sync(0xffffffffu, mnew1, off));
    }
    float mn0 = fmaxf(m_i[0], mnew0);
    float mn1 = fmaxf(m_i[1], mnew1);
    float corr0 = __expf(m_i[0] - mn0);
    float corr1 = __expf(m_i[1] - mn1);
    m_i[0] = mn0;
    m_i[1] = mn1;

    float rs0 = 0.f, rs1 = 0.f;
#pragma unroll
    for (int t = 0; t < 8; t++) {
      sacc[t][0] = __expf(sacc[t][0] - mn0);
      sacc[t][1] = __expf(sacc[t][1] - mn0);
      sacc[t][2] = __expf(sacc[t][2] - mn1);
      sacc[t][3] = __expf(sacc[t][3] - mn1);
      rs0 += sacc[t][0] + sacc[t][1];
      rs1 += sacc[t][2] + sacc[t][3];
    }
#pragma unroll
    for (int off = 1; off <= 2; off <<= 1) {
      rs0 += __shfl_xor_sync(0xffffffffu, rs0, off);
      rs1 += __shfl_xor_sync(0xffffffffu, rs1, off);
    }
    l_i[0] = l_i[0] * corr0 + rs0;
    l_i[1] = l_i[1] * corr1 + rs1;

#pragma unroll
    for (int t = 0; t < 8; t++) {
      oacc[t][0] *= corr0; oacc[t][1] *= corr0;
      oacc[t][2] *= corr1; oacc[t][3] *= corr1;
      // tf32 round P in place
      sacc[t][0] = tf32_rna(sacc[t][0]);
      sacc[t][1] = tf32_rna(sacc[t][1]);
      sacc[t][2] = tf32_rna(sacc[t][2]);
      sacc[t][3] = tf32_rna(sacc[t][3]);
    }

    // --- O += P V  (A-frag from P accumulator via quad shuffles) ---
    const int srcA = (lane & ~3) | (tg >> 1);
    const int srcB = srcA + 2;
    const bool odd = (tg & 1);
#pragma unroll
    for (int j = 0; j < 8; j++) {
      uint32_t p0 = __float_as_uint(sacc[j][0]);
      uint32_t p1 = __float_as_uint(sacc[j][1]);
      uint32_t p2 = __float_as_uint(sacc[j][2]);
      uint32_t p3 = __float_as_uint(sacc[j][3]);
      uint32_t t0 = __shfl_sync(0xffffffffu, p0, srcA);
      uint32_t t1 = __shfl_sync(0xffffffffu, p1, srcA);
      uint32_t t2 = __shfl_sync(0xffffffffu, p2, srcA);
      uint32_t t3 = __shfl_sync(0xffffffffu, p3, srcA);
      uint32_t t4 = __shfl_sync(0xffffffffu, p0, srcB);
      uint32_t t5 = __shfl_sync(0xffffffffu, p1, srcB);
      uint32_t t6 = __shfl_sync(0xffffffffu, p2, srcB);
      uint32_t t7 = __shfl_sync(0xffffffffu, p3, srcB);
      uint32_t af[4];
      af[0] = odd ? t1 : t0;
      af[1] = odd ? t3 : t2;
      af[2] = odd ? t5 : t4;
      af[3] = odd ? t7 : t6;
#pragma unroll
      for (int t = 0; t < 8; t++) {
        uint32_t bf[2];
        bf[0] = vsu[(8 * j + tg) * KVSTRIDE + 8 * t + g];
        bf[1] = vsu[(8 * j + tg + 4) * KVSTRIDE + 8 * t + g];
        mma_16n8k8(oacc[t], af, bf);
      }
    }
    __syncthreads();  // all reads of buf done before it is re-staged
  }

  // --- Epilogue: ctx[b][q][h*64+d] = O / l ---
  float inv0 = 1.f / l_i[0];
  float inv1 = 1.f / l_i[1];
  float* cp0 = g_ctx + ((size_t)b * CN + q0) * CD + h * CKD;
#pragma unroll
  for (int t = 0; t < 8; t++) {
    *(float2*)(cp0 + t * 8 + 2 * tg) =
        make_float2(oacc[t][0] * inv0, oacc[t][1] * inv0);
    *(float2*)(cp0 + (size_t)8 * CD + t * 8 + 2 * tg) =
        make_float2(oacc[t][2] * inv1, oacc[t][3] * inv1);
  }
}

// ---------------------------------------------------------------------------

extern "C" void kernel_launch(void* const* d_in, const int* in_sizes, int n_in,
                              void* d_out, int out_size) {
  const float* x = (const float*)d_in[0];
  const float* leadlag_bias = (const float*)d_in[1];
  const float* Wq = (const float*)d_in[2];
  const float* Wk = (const float*)d_in[3];
  const float* Wv = (const float*)d_in[4];
  const float* Wo = (const float*)d_in[5];
  const float* bias_scale = (const float*)d_in[6];
  float* out = (float*)d_out;

  (void)in_sizes; (void)n_in; (void)out_size;

  static int attr_set = 0;
  if (!attr_set) {
    cudaFuncSetAttribute(attn_mma_kernel,
                         cudaFuncAttributeMaxDynamicSharedMemorySize,
                         ATTN_SMEM_BYTES);
    attr_set = 1;
  }

  transpose_w_kernel<<<dim3(CD / 32, CD / 32, 4), dim3(32, 8)>>>(Wq, Wk, Wv, Wo);
  qkv_mma_kernel<<<dim3(CD / 128, CM / 128, 3), 256>>>(x);
  attn_mma_kernel<<<dim3(CN / 128, CH, CB), 256, ATTN_SMEM_BYTES>>>(
      leadlag_bias, bias_scale);
  out_mma_kernel<<<dim3(CD / 128, CM / 128, 1), 256>>>(out);
}

// round 5
// speedup vs baseline: 3.2254x; 2.0570x over previous
#include <cuda_runtime.h>
#include <cstdint>

#define CB 16
#define CN 1024
#define CD 512
#define CH 8
#define CKD 64
#define CM (CB * CN)  // 16384
#define LOG2E 1.4426950408889634f

// Scratch (alloc-free rule: __device__ globals)
// g_Q: [b,h,n,d'] d' pair-permuted, values pre-scaled by 0.125*log2e, tf32-rounded
// g_K: [b,h,n,d'] d' pair-permuted, tf32-rounded
// g_V: stored TRANSPOSED as Vt [b,h][d][n'] n' pair-permuted, tf32-rounded
__device__ float g_Q[(size_t)CB * CH * CN * CKD];
__device__ float g_K[(size_t)CB * CH * CN * CKD];
__device__ float g_V[(size_t)CB * CH * CN * CKD];
__device__ float g_ctx[(size_t)CM * CD];            // [B,N,H*KD]
__device__ float g_Wt[4 * CD * CD];                 // transposed weights [n][k]

// ---------------------------------------------------------------------------
// Helpers
// ---------------------------------------------------------------------------

__device__ __forceinline__ float tf32_rna(float x) {
  uint32_t r;
  asm("cvt.rna.tf32.f32 %0, %1;" : "=r"(r) : "f"(x));
  return __uint_as_float(r);
}

__device__ __forceinline__ float ex2f(float x) {
  float y;
  asm("ex2.approx.f32 %0, %1;" : "=f"(y) : "f"(x));
  return y;
}

// pair permutation within an 8-block: (c, c+4) become adjacent
__device__ __forceinline__ int perm8(int x) {
  return ((x & 3) << 1) | ((x >> 2) & 1);
}

__device__ __forceinline__ void mma_16n8k8(float* c, const uint32_t* a,
                                           const uint32_t* b) {
  asm volatile(
      "mma.sync.aligned.m16n8k8.row.col.f32.tf32.tf32.f32 "
      "{%0,%1,%2,%3}, {%4,%5,%6,%7}, {%8,%9}, {%0,%1,%2,%3};"
      : "+f"(c[0]), "+f"(c[1]), "+f"(c[2]), "+f"(c[3])
      : "r"(a[0]), "r"(a[1]), "r"(a[2]), "r"(a[3]), "r"(b[0]), "r"(b[1]));
}

__device__ __forceinline__ void cp16(float* dst, const float* src) {
  uint32_t d = (uint32_t)__cvta_generic_to_shared(dst);
  asm volatile("cp.async.cg.shared.global [%0], [%1], 16;" ::"r"(d), "l"(src)
               : "memory");
}
#define CP_COMMIT() asm volatile("cp.async.commit_group;" ::: "memory")
#define CP_WAIT(n) asm volatile("cp.async.wait_group %0;" ::"n"(n) : "memory")

// ---------------------------------------------------------------------------
// Weight transpose: Wt[n][k] = W[k][n]  (4 matrices, 512x512)
// ---------------------------------------------------------------------------

__global__ void transpose_w_kernel(const float* __restrict__ Wq,
                                   const float* __restrict__ Wk,
                                   const float* __restrict__ Wv,
                                   const float* __restrict__ Wo) {
  __shared__ float t[32][33];
  const float* W = (blockIdx.z == 0) ? Wq : (blockIdx.z == 1) ? Wk
                   : (blockIdx.z == 2) ? Wv : Wo;
  float* Out = g_Wt + (size_t)blockIdx.z * CD * CD;
  int n0 = blockIdx.x * 32, k0 = blockIdx.y * 32;
  int tx = threadIdx.x, ty = threadIdx.y;
#pragma unroll
  for (int s = 0; s < 4; s++)
    t[ty + s * 8][tx] = W[(size_t)(k0 + ty + s * 8) * CD + n0 + tx];
  __syncthreads();
#pragma unroll
  for (int s = 0; s < 4; s++)
    Out[(size_t)(n0 + ty + s * 8) * CD + k0 + tx] = t[tx][ty + s * 8];
}

// ---------------------------------------------------------------------------
// tf32 mma.sync GEMM: C[16384,512] = A * Bt^T
// modes: 0=Q (scale+rna+perm d), 1=K (rna+perm d), 2=V (rna, transposed+perm n),
//        3=plain row-major
// ---------------------------------------------------------------------------

#define BK 16
#define LDSROW 20

__device__ __forceinline__ void gemm_mma_tile(const float* __restrict__ A,
                                              const float* __restrict__ Bt,
                                              float* __restrict__ Out,
                                              int mode) {
  __shared__ float As[2][128 * LDSROW];
  __shared__ float Bs[2][128 * LDSROW];

  const int tid = threadIdx.x;
  const int lane = tid & 31;
  const int warp = tid >> 5;
  const int wm = warp & 3;
  const int wn = warp >> 2;
  const int g = lane >> 2;
  const int tg = lane & 3;

  const int col0 = blockIdx.x * 128;
  const int row0 = blockIdx.y * 128;

  const int lr = tid >> 2;
  const int lc = (tid & 3) * 4;

  float acc[2][8][4];
#pragma unroll
  for (int mt = 0; mt < 2; mt++)
#pragma unroll
    for (int nt = 0; nt < 8; nt++)
#pragma unroll
      for (int i = 0; i < 4; i++) acc[mt][nt][i] = 0.f;

  float4 ra0, ra1, rb0, rb1;
  {
    const float* ap = A + (size_t)(row0 + lr) * CD + lc;
    const float* bp = Bt + (size_t)(col0 + lr) * CD + lc;
    ra0 = *(const float4*)ap;
    ra1 = *(const float4*)(ap + (size_t)64 * CD);
    rb0 = *(const float4*)bp;
    rb1 = *(const float4*)(bp + (size_t)64 * CD);
  }

  for (int kt = 0; kt < CD / BK; kt++) {
    const int buf = kt & 1;
    float* as = As[buf];
    float* bs = Bs[buf];
    {
      int o0 = lr * LDSROW + lc;
      int o1 = (lr + 64) * LDSROW + lc;
      as[o0 + 0] = tf32_rna(ra0.x); as[o0 + 1] = tf32_rna(ra0.y);
      as[o0 + 2] = tf32_rna(ra0.z); as[o0 + 3] = tf32_rna(ra0.w);
      as[o1 + 0] = tf32_rna(ra1.x); as[o1 + 1] = tf32_rna(ra1.y);
      as[o1 + 2] = tf32_rna(ra1.z); as[o1 + 3] = tf32_rna(ra1.w);
      bs[o0 + 0] = tf32_rna(rb0.x); bs[o0 + 1] = tf32_rna(rb0.y);
      bs[o0 + 2] = tf32_rna(rb0.z); bs[o0 + 3] = tf32_rna(rb0.w);
      bs[o1 + 0] = tf32_rna(rb1.x); bs[o1 + 1] = tf32_rna(rb1.y);
      bs[o1 + 2] = tf32_rna(rb1.z); bs[o1 + 3] = tf32_rna(rb1.w);
    }
    __syncthreads();

    if (kt + 1 < CD / BK) {
      int k0 = (kt + 1) * BK;
      const float* ap = A + (size_t)(row0 + lr) * CD + k0 + lc;
      const float* bp = Bt + (size_t)(col0 + lr) * CD + k0 + lc;
      ra0 = *(const float4*)ap;
      ra1 = *(const float4*)(ap + (size_t)64 * CD);
      rb0 = *(const float4*)bp;
      rb1 = *(const float4*)(bp + (size_t)64 * CD);
    }

    const uint32_t* asu = (const uint32_t*)as;
    const uint32_t* bsu = (const uint32_t*)bs;
#pragma unroll
    for (int k8 = 0; k8 < 2; k8++) {
      const int kb = k8 * 8 + tg;
      uint32_t af[2][4];
#pragma unroll
      for (int mt = 0; mt < 2; mt++) {
        int r = wm * 32 + mt * 16 + g;
        af[mt][0] = asu[r * LDSROW + kb];
        af[mt][1] = asu[(r + 8) * LDSROW + kb];
        af[mt][2] = asu[r * LDSROW + kb + 4];
        af[mt][3] = asu[(r + 8) * LDSROW + kb + 4];
      }
#pragma unroll
      for (int nt = 0; nt < 8; nt++) {
        int n = wn * 64 + nt * 8 + g;
        uint32_t bf[2];
        bf[0] = bsu[n * LDSROW + kb];
        bf[1] = bsu[n * LDSROW + kb + 4];
        mma_16n8k8(acc[0][nt], af[0], bf);
        mma_16n8k8(acc[1][nt], af[1], bf);
      }
    }
    __syncthreads();
  }

  const float qs = 0.125f * LOG2E;
#pragma unroll
  for (int mt = 0; mt < 2; mt++) {
#pragma unroll
    for (int nt = 0; nt < 8; nt++) {
      int R = row0 + wm * 32 + mt * 16 + g;
      int C = col0 + wn * 64 + nt * 8 + 2 * tg;
      float2 v0 = make_float2(acc[mt][nt][0], acc[mt][nt][1]);
      float2 v1 = make_float2(acc[mt][nt][2], acc[mt][nt][3]);
      if (mode <= 1) {  // Q or K -> [b,h,n,d'] with d' permuted
        int h = C >> 6, dr = C & 63;
        int d0 = (dr & ~7) | perm8(dr & 7);
        int d1 = (dr & ~7) | perm8((dr & 7) + 1);
        if (mode == 0) {
          v0.x *= qs; v0.y *= qs; v1.x *= qs; v1.y *= qs;
        }
        int bb0 = R >> 10, n0 = R & 1023;
        int bb1 = (R + 8) >> 10, n1 = (R + 8) & 1023;
        size_t b0 = (((size_t)bb0 * CH + h) * CN + n0) * CKD;
        size_t b1 = (((size_t)bb1 * CH + h) * CN + n1) * CKD;
        Out[b0 + d0] = tf32_rna(v0.x);
        Out[b0 + d1] = tf32_rna(v0.y);
        Out[b1 + d0] = tf32_rna(v1.x);
        Out[b1 + d1] = tf32_rna(v1.y);
      } else if (mode == 2) {  // V -> Vt [b,h][d][n'] with n' permuted
        int h = C >> 6, d = C & 63;
        int bb = R >> 10, nn = R & 1023;
        int colp = (nn & ~7) | perm8(nn & 7);  // (R+8) -> colp+8, same bb
        size_t base = (((size_t)bb * CH + h) * CKD + d) * CN;
        Out[base + colp] = tf32_rna(v0.x);
        Out[base + CN + colp] = tf32_rna(v0.y);
        Out[base + colp + 8] = tf32_rna(v1.x);
        Out[base + CN + colp + 8] = tf32_rna(v1.y);
      } else {  // plain row-major (final output)
        *(float2*)(Out + (size_t)R * CD + C) = v0;
        *(float2*)(Out + (size_t)(R + 8) * CD + C) = v1;
      }
    }
  }
}

__global__ __launch_bounds__(256) void qkv_mma_kernel(const float* __restrict__ x) {
  const float* Bt = g_Wt + (size_t)blockIdx.z * CD * CD;
  float* Out = (blockIdx.z == 0) ? g_Q : (blockIdx.z == 1) ? g_K : g_V;
  gemm_mma_tile(x, Bt, Out, (int)blockIdx.z);
}

__global__ __launch_bounds__(256) void out_mma_kernel(float* __restrict__ out) {
  gemm_mma_tile(g_ctx, g_Wt + (size_t)3 * CD * CD, out, 3);
}

// ---------------------------------------------------------------------------
// mma.sync flash attention: CTA = (qb 128 rows, h, b); 8 warps x m16.
// Q persistent in smem (stride 72). K and Vt tiles of 64 cp.async
// double-buffered (stride 72). Pair-permuted layouts -> all B-frags LDS.64.
// log2-domain softmax (ex2.approx).
// ---------------------------------------------------------------------------

#define KVSTRIDE 72
#define QSMF (128 * KVSTRIDE)           // 9216 floats
#define KVT (64 * KVSTRIDE)             // 4608 floats
#define ATTN_SMEM_BYTES ((QSMF + 4 * KVT) * 4)  // 110592 B

__device__ __forceinline__ void stage_kv(const float* __restrict__ Kg,
                                         const float* __restrict__ Vtg,
                                         float* kdst, float* vdst, int kb,
                                         int tid) {
#pragma unroll
  for (int it = 0; it < 4; it++) {
    int j = tid + it * 256;
    int row = j >> 4;          // K: kv row; V: d row
    int c4 = (j & 15) * 4;
    cp16(kdst + row * KVSTRIDE + c4, Kg + (size_t)(kb * 64 + row) * CKD + c4);
    cp16(vdst + row * KVSTRIDE + c4, Vtg + (size_t)row * CN + kb * 64 + c4);
  }
  CP_COMMIT();
}

__global__ __launch_bounds__(256, 2) void attn_mma_kernel(
    const float* __restrict__ bias, const float* __restrict__ bias_scale) {
  extern __shared__ float sm[];
  float* Qs = sm;
  float* Kbuf[2] = {sm + QSMF, sm + QSMF + 2 * KVT};
  float* Vbuf[2] = {sm + QSMF + KVT, sm + QSMF + 3 * KVT};

  const int qb = blockIdx.x;
  const int h = blockIdx.y;
  const int b = blockIdx.z;
  const int tid = threadIdx.x;
  const int lane = tid & 31;
  const int warp = tid >> 5;
  const int g = lane >> 2;
  const int tg = lane & 3;
  const int m0 = warp * 16;

  const float bscale = bias_scale[h] * LOG2E;
  const float* Qg = g_Q + (((size_t)b * CH + h) * CN + (size_t)qb * 128) * CKD;
  const float* Kg = g_K + ((size_t)b * CH + h) * CN * CKD;
  const float* Vtg = g_V + ((size_t)b * CH + h) * CKD * CN;

  // Stage Q (already scaled/rounded/permuted in gmem)
#pragma unroll
  for (int it = 0; it < 8; it++) {
    int j = tid + it * 256;
    int row = j >> 4;
    int c4 = (j & 15) * 4;
    *(float4*)(Qs + row * KVSTRIDE + c4) =
        *(const float4*)(Qg + (size_t)row * CKD + c4);
  }
  stage_kv(Kg, Vtg, Kbuf[0], Vbuf[0], 0, tid);
  __syncthreads();

  float oacc[8][4];
#pragma unroll
  for (int t = 0; t < 8; t++)
#pragma unroll
    for (int c = 0; c < 4; c++) oacc[t][c] = 0.f;
  float m_i[2] = {-1e30f, -1e30f};
  float l_i[2] = {0.f, 0.f};

  const int q0 = qb * 128 + m0 + g;
  const float2* qp = (const float2*)Qs;
  const int qr0 = (m0 + g) * (KVSTRIDE / 2);
  const int qr1 = (m0 + 8 + g) * (KVSTRIDE / 2);

  for (int kb = 0; kb < 16; kb++) {
    const int buf = kb & 1;
    if (kb + 1 < 16)
      stage_kv(Kg, Vtg, Kbuf[buf ^ 1], Vbuf[buf ^ 1], kb + 1, tid);
    if (kb + 1 < 16) { CP_WAIT(1); } else { CP_WAIT(0); }
    __syncthreads();

    const float2* kp = (const float2*)Kbuf[buf];
    const float2* vp = (const float2*)Vbuf[buf];

    // --- S = Q K^T (log2-domain logits) ---
    float sacc[8][4];
#pragma unroll
    for (int t = 0; t < 8; t++)
#pragma unroll
      for (int c = 0; c < 4; c++) sacc[t][c] = 0.f;

#pragma unroll
    for (int j = 0; j < 8; j++) {
      float2 qa = qp[qr0 + j * 4 + tg];
      float2 qb2 = qp[qr1 + j * 4 + tg];
      uint32_t af[4] = {__float_as_uint(qa.x), __float_as_uint(qb2.x),
                        __float_as_uint(qa.y), __float_as_uint(qb2.y)};
#pragma unroll
      for (int t = 0; t < 8; t++) {
        float2 kv = kp[(t * 8 + g) * (KVSTRIDE / 2) + j * 4 + tg];
        uint32_t bf[2] = {__float_as_uint(kv.x), __float_as_uint(kv.y)};
        mma_16n8k8(sacc[t], af, bf);
      }
    }

    // --- bias + online softmax (base-2) ---
    const float* bp = bias + (size_t)q0 * CN + kb * 64;
    float mnew0 = -1e30f, mnew1 = -1e30f;
#pragma unroll
    for (int t = 0; t < 8; t++) {
      float2 bv0 = *(const float2*)(bp + t * 8 + 2 * tg);
      float2 bv1 = *(const float2*)(bp + (size_t)8 * CN + t * 8 + 2 * tg);
      sacc[t][0] = fmaf(bv0.x, bscale, sacc[t][0]);
      sacc[t][1] = fmaf(bv0.y, bscale, sacc[t][1]);
      sacc[t][2] = fmaf(bv1.x, bscale, sacc[t][2]);
      sacc[t][3] = fmaf(bv1.y, bscale, sacc[t][3]);
      mnew0 = fmaxf(mnew0, fmaxf(sacc[t][0], sacc[t][1]));
      mnew1 = fmaxf(mnew1, fmaxf(sacc[t][2], sacc[t][3]));
    }
#pragma unroll
    for (int off = 1; off <= 2; off <<= 1) {
      mnew0 = fmaxf(mnew0, __shfl_xor_sync(0xffffffffu, mnew0, off));
      mnew1 = fmaxf(mnew1, __shfl_xor_sync(0xffffffffu, mnew1, off));
    }
    float mn0 = fmaxf(m_i[0], mnew0);
    float mn1 = fmaxf(m_i[1], mnew1);
    float corr0 = ex2f(m_i[0] - mn0);
    float corr1 = ex2f(m_i[1] - mn1);
    m_i[0] = mn0;
    m_i[1] = mn1;

    float rs0 = 0.f, rs1 = 0.f;
#pragma unroll
    for (int t = 0; t < 8; t++) {
      sacc[t][0] = ex2f(sacc[t][0] - mn0);
      sacc[t][1] = ex2f(sacc[t][1] - mn0);
      sacc[t][2] = ex2f(sacc[t][2] - mn1);
      sacc[t][3] = ex2f(sacc[t][3] - mn1);
      rs0 += sacc[t][0] + sacc[t][1];
      rs1 += sacc[t][2] + sacc[t][3];
    }
#pragma unroll
    for (int off = 1; off <= 2; off <<= 1) {
      rs0 += __shfl_xor_sync(0xffffffffu, rs0, off);
      rs1 += __shfl_xor_sync(0xffffffffu, rs1, off);
    }
    l_i[0] = l_i[0] * corr0 + rs0;
    l_i[1] = l_i[1] * corr1 + rs1;

#pragma unroll
    for (int t = 0; t < 8; t++) {
      oacc[t][0] *= corr0; oacc[t][1] *= corr0;
      oacc[t][2] *= corr1; oacc[t][3] *= corr1;
    }

    // --- O += P V  (A-frag from P accumulator via quad shuffles) ---
    const int srcA = (lane & ~3) | (tg >> 1);
    const int srcB = srcA + 2;
    const bool odd = (tg & 1);
#pragma unroll
    for (int j = 0; j < 8; j++) {
      uint32_t p0 = __float_as_uint(sacc[j][0]);
      uint32_t p1 = __float_as_uint(sacc[j][1]);
      uint32_t p2 = __float_as_uint(sacc[j][2]);
      uint32_t p3 = __float_as_uint(sacc[j][3]);
      uint32_t t0 = __shfl_sync(0xffffffffu, p0, srcA);
      uint32_t t1 = __shfl_sync(0xffffffffu, p1, srcA);
      uint32_t t2 = __shfl_sync(0xffffffffu, p2, srcA);
      uint32_t t3 = __shfl_sync(0xffffffffu, p3, srcA);
      uint32_t t4 = __shfl_sync(0xffffffffu, p0, srcB);
      uint32_t t5 = __shfl_sync(0xffffffffu, p1, srcB);
      uint32_t t6 = __shfl_sync(0xffffffffu, p2, srcB);
      uint32_t t7 = __shfl_sync(0xffffffffu, p3, srcB);
      uint32_t af[4];
      af[0] = odd ? t1 : t0;
      af[1] = odd ? t3 : t2;
      af[2] = odd ? t5 : t4;
      af[3] = odd ? t7 : t6;
#pragma unroll
      for (int t = 0; t < 8; t++) {
        float2 vv = vp[(t * 8 + g) * (KVSTRIDE / 2) + j * 4 + tg];
        uint32_t bf[2] = {__float_as_uint(vv.x), __float_as_uint(vv.y)};
        mma_16n8k8(oacc[t], af, bf);
      }
    }
    __syncthreads();  // all reads of buf done before it is re-staged
  }

  // --- Epilogue: ctx[b][q][h*64+d] = O / l ---
  float inv0 = 1.f / l_i[0];
  float inv1 = 1.f / l_i[1];
  float* cp0 = g_ctx + ((size_t)b * CN + q0) * CD + h * CKD;
#pragma unroll
  for (int t = 0; t < 8; t++) {
    *(float2*)(cp0 + t * 8 + 2 * tg) =
        make_float2(oacc[t][0] * inv0, oacc[t][1] * inv0);
    *(float2*)(cp0 + (size_t)8 * CD + t * 8 + 2 * tg) =
        make_float2(oacc[t][2] * inv1, oacc[t][3] * inv1);
  }
}

// ---------------------------------------------------------------------------

extern "C" void kernel_launch(void* const* d_in, const int* in_sizes, int n_in,
                              void* d_out, int out_size) {
  const float* x = (const float*)d_in[0];
  const float* leadlag_bias = (const float*)d_in[1];
  const float* Wq = (const float*)d_in[2];
  const float* Wk = (const float*)d_in[3];
  const float* Wv = (const float*)d_in[4];
  const float* Wo = (const float*)d_in[5];
  const float* bias_scale = (const float*)d_in[6];
  float* out = (float*)d_out;

  (void)in_sizes; (void)n_in; (void)out_size;

  static int attr_set = 0;
  if (!attr_set) {
    cudaFuncSetAttribute(attn_mma_kernel,
                         cudaFuncAttributeMaxDynamicSharedMemorySize,
                         ATTN_SMEM_BYTES);
    attr_set = 1;
  }

  transpose_w_kernel<<<dim3(CD / 32, CD / 32, 4), dim3(32, 8)>>>(Wq, Wk, Wv, Wo);
  qkv_mma_kernel<<<dim3(CD / 128, CM / 128, 3), 256>>>(x);
  attn_mma_kernel<<<dim3(CN / 128, CH, CB), 256, ATTN_SMEM_BYTES>>>(
      leadlag_bias, bias_scale);
  out_mma_kernel<<<dim3(CD / 128, CM / 128, 1), 256>>>(out);
}